// round 2
// baseline (speedup 1.0000x reference)
#include <cuda_runtime.h>
#include <math.h>

#define NN 4096
#define KN 48
#define CC 128
#define EC 384
#define HD 512

// ---------------- scratch (device globals: allocation-free) ----------------
__device__ float g_node_pre[NN * CC];   // node @ W1a^T + b_m1
__device__ float g_S[NN * CC];          // sum_k attn * h2
__device__ float g_A[NN];               // sum_k attn
__device__ float g_X[NN * CC];          // post-LN1 x
__device__ float g_H[NN * HD];          // gelu(x @ Wd1^T + bd1)

__device__ __forceinline__ float gelu_f(float x) {
    return 0.5f * x * (1.0f + erff(x * 0.70710678118654752440f));
}

// ======================= K0: node_pre = node @ W1a^T + b1 ==================
// M=4096 (32 rows/block), N=128, K=128
__global__ __launch_bounds__(256)
void k0_node_pre(const float* __restrict__ node, const float* __restrict__ W1,
                 const float* __restrict__ b1) {
    extern __shared__ float sm[];
    float* sX = sm;           // 32*128
    float* sW = sm + 4096;    // 128*128  sW[k][c] = W1[c*512 + k]
    const int tid = threadIdx.x, tx = tid & 15, ty = tid >> 4;
    const int n0 = blockIdx.x * 32;

#pragma unroll
    for (int m = 0; m < 4; ++m) {
        int f4 = tid + 256 * m;              // 0..1023
        int r = f4 >> 5, c4 = f4 & 31;
        *(float4*)(sX + r * 128 + c4 * 4) =
            *(const float4*)(node + (size_t)(n0 + r) * 128 + c4 * 4);
    }
#pragma unroll
    for (int m = 0; m < 16; ++m) {
        int idx = tid + 256 * m;             // 0..4095
        int c = idx & 127, k4 = idx >> 7;
        float4 v = *(const float4*)(W1 + (size_t)c * 512 + k4 * 4);
        sW[(k4 * 4 + 0) * 128 + c] = v.x;
        sW[(k4 * 4 + 1) * 128 + c] = v.y;
        sW[(k4 * 4 + 2) * 128 + c] = v.z;
        sW[(k4 * 4 + 3) * 128 + c] = v.w;
    }
    __syncthreads();

    float acc[2][8] = {};
#pragma unroll
    for (int kk = 0; kk < 128; kk += 4) {
        float a[2][4];
#pragma unroll
        for (int i = 0; i < 2; ++i) {
            float4 t = *(float4*)(sX + (ty + 16 * i) * 128 + kk);
            a[i][0] = t.x; a[i][1] = t.y; a[i][2] = t.z; a[i][3] = t.w;
        }
#pragma unroll
        for (int q = 0; q < 4; ++q) {
            float4 b0 = *(float4*)(sW + (kk + q) * 128 + tx * 8);
            float4 b1v = *(float4*)(sW + (kk + q) * 128 + tx * 8 + 4);
            float bb[8] = {b0.x, b0.y, b0.z, b0.w, b1v.x, b1v.y, b1v.z, b1v.w};
#pragma unroll
            for (int i = 0; i < 2; ++i)
#pragma unroll
                for (int j = 0; j < 8; ++j) acc[i][j] += a[i][q] * bb[j];
        }
    }
#pragma unroll
    for (int i = 0; i < 2; ++i) {
        int r = n0 + ty + 16 * i;
#pragma unroll
        for (int j = 0; j < 8; ++j) {
            int c = tx * 8 + j;
            g_node_pre[(size_t)r * 128 + c] = acc[i][j] + b1[c];
        }
    }
}

// ======================= K1: per-node edge message kernel ===================
// block = one node n. GEMM1b (48x384 @ 384x128) + gelu, GEMM2 (48x128 @ 128x128)
// + gelu, attn-weighted reduce over 48 -> g_S, g_A.
__global__ __launch_bounds__(256, 2)
void k1_edges(const float* __restrict__ edge, const float* __restrict__ attn,
              const float* __restrict__ W1, const float* __restrict__ W2,
              const float* __restrict__ b2) {
    extern __shared__ float sm[];
    float* sU = sm;                 // 16384 floats: union{sA,sB} / sB2
    float* sH = sm + 16384;         // 6144: h1 (48x128), later sPart
    float* sNP = sm + 16384 + 6144; // 128
    float* sAt = sNP + 128;         // 64 (48 used)
    float* sA = sU;                 // 48*64
    float* sB = sU + 3072;          // 64*128

    const int n = blockIdx.x;
    const int tid = threadIdx.x;
    const int tx = tid & 15;
    const int ty = tid >> 4;
    const float* eb = edge + (size_t)n * (KN * EC);

    if (tid < 128) sNP[tid] = g_node_pre[(size_t)n * 128 + tid];
    if (tid < KN) sAt[tid] = attn[(size_t)n * KN + tid];

    float acc[3][8] = {};

    // ---- GEMM1b over edge context, k-tiles of 64 ----
    for (int kt = 0; kt < 6; ++kt) {
        __syncthreads();
#pragma unroll
        for (int m = 0; m < 3; ++m) {
            int f4 = tid + 256 * m;          // 0..767
            int r = f4 >> 4, c4 = f4 & 15;
            *(float4*)(sA + r * 64 + c4 * 4) =
                *(const float4*)(eb + (size_t)r * EC + kt * 64 + c4 * 4);
        }
#pragma unroll
        for (int m = 0; m < 8; ++m) {
            int idx = tid + 256 * m;         // 0..2047
            int c = idx & 127, d4 = idx >> 7;
            float4 v = *(const float4*)(W1 + (size_t)c * 512 + 128 + kt * 64 + d4 * 4);
            sB[(d4 * 4 + 0) * 128 + c] = v.x;
            sB[(d4 * 4 + 1) * 128 + c] = v.y;
            sB[(d4 * 4 + 2) * 128 + c] = v.z;
            sB[(d4 * 4 + 3) * 128 + c] = v.w;
        }
        __syncthreads();
#pragma unroll
        for (int kk = 0; kk < 64; kk += 4) {
            float a[3][4];
#pragma unroll
            for (int i = 0; i < 3; ++i) {
                float4 t = *(float4*)(sA + (ty + 16 * i) * 64 + kk);
                a[i][0] = t.x; a[i][1] = t.y; a[i][2] = t.z; a[i][3] = t.w;
            }
#pragma unroll
            for (int q = 0; q < 4; ++q) {
                float4 b0 = *(float4*)(sB + (kk + q) * 128 + tx * 8);
                float4 b1v = *(float4*)(sB + (kk + q) * 128 + tx * 8 + 4);
                float bb[8] = {b0.x, b0.y, b0.z, b0.w, b1v.x, b1v.y, b1v.z, b1v.w};
#pragma unroll
                for (int i = 0; i < 3; ++i)
#pragma unroll
                    for (int j = 0; j < 8; ++j) acc[i][j] += a[i][q] * bb[j];
            }
        }
    }

    // ---- epilogue 1: h1 = gelu(node_pre + acc) -> sH ----
#pragma unroll
    for (int i = 0; i < 3; ++i) {
        int r = ty + 16 * i;
        float h[8];
#pragma unroll
        for (int j = 0; j < 8; ++j) h[j] = gelu_f(acc[i][j] + sNP[tx * 8 + j]);
        *(float4*)(sH + r * 128 + tx * 8) = make_float4(h[0], h[1], h[2], h[3]);
        *(float4*)(sH + r * 128 + tx * 8 + 4) = make_float4(h[4], h[5], h[6], h[7]);
    }
    __syncthreads();

    // ---- load W2^T into sU: sU[c][d] = W2[d*128 + c] ----
#pragma unroll
    for (int m = 0; m < 16; ++m) {
        int idx = tid + 256 * m;             // 0..4095
        int d = idx & 127, c4 = idx >> 7;
        float4 v = *(const float4*)(W2 + (size_t)d * 128 + c4 * 4);
        sU[(c4 * 4 + 0) * 128 + d] = v.x;
        sU[(c4 * 4 + 1) * 128 + d] = v.y;
        sU[(c4 * 4 + 2) * 128 + d] = v.z;
        sU[(c4 * 4 + 3) * 128 + d] = v.w;
    }
    __syncthreads();

    // ---- GEMM2: acc2 = h1 @ W2^T ----
    float acc2[3][8] = {};
#pragma unroll
    for (int kk = 0; kk < 128; kk += 4) {
        float a[3][4];
#pragma unroll
        for (int i = 0; i < 3; ++i) {
            float4 t = *(float4*)(sH + (ty + 16 * i) * 128 + kk);
            a[i][0] = t.x; a[i][1] = t.y; a[i][2] = t.z; a[i][3] = t.w;
        }
#pragma unroll
        for (int q = 0; q < 4; ++q) {
            float4 b0 = *(float4*)(sU + (kk + q) * 128 + tx * 8);
            float4 b1v = *(float4*)(sU + (kk + q) * 128 + tx * 8 + 4);
            float bb[8] = {b0.x, b0.y, b0.z, b0.w, b1v.x, b1v.y, b1v.z, b1v.w};
#pragma unroll
            for (int i = 0; i < 3; ++i)
#pragma unroll
                for (int j = 0; j < 8; ++j) acc2[i][j] += a[i][q] * bb[j];
        }
    }

    // ---- epilogue 2: h2 = gelu(acc2 + b2); weighted partial over rows ----
    float w0 = sAt[ty], w1 = sAt[ty + 16], w2 = sAt[ty + 32];
    float4 b2a = *(const float4*)(b2 + tx * 8);
    float4 b2b = *(const float4*)(b2 + tx * 8 + 4);
    float b2v[8] = {b2a.x, b2a.y, b2a.z, b2a.w, b2b.x, b2b.y, b2b.z, b2b.w};
    float part[8];
#pragma unroll
    for (int j = 0; j < 8; ++j) {
        float p0 = gelu_f(acc2[0][j] + b2v[j]);
        float p1 = gelu_f(acc2[1][j] + b2v[j]);
        float p2 = gelu_f(acc2[2][j] + b2v[j]);
        part[j] = w0 * p0 + w1 * p1 + w2 * p2;
    }
    __syncthreads();                 // all sH reads done -> reuse as sPart
    float* sPart = sH;               // 16 x 128
    *(float4*)(sPart + ty * 128 + tx * 8) = make_float4(part[0], part[1], part[2], part[3]);
    *(float4*)(sPart + ty * 128 + tx * 8 + 4) = make_float4(part[4], part[5], part[6], part[7]);
    __syncthreads();

    if (tid < 128) {
        float s = 0.f;
#pragma unroll
        for (int t = 0; t < 16; ++t) s += sPart[t * 128 + tid];
        g_S[(size_t)n * 128 + tid] = s;
    }
    if (tid == 0) {
        float s = 0.f;
#pragma unroll
        for (int k = 0; k < KN; ++k) s += sAt[k];
        g_A[n] = s;
    }
}

// ========= K2: x = LN1(node + (W3 @ S + A*b3)/30) -> g_X (fused) ===========
__global__ __launch_bounds__(256)
void k2_ln1(const float* __restrict__ node, const float* __restrict__ W3,
            const float* __restrict__ b3, const float* __restrict__ g1,
            const float* __restrict__ be1) {
    extern __shared__ float sm[];
    float* sS = sm;            // 32*128
    float* sW = sm + 4096;     // 128*128  sW[c][d] = W3[d*128 + c]
    float* sRs = sm + 20480;   // 512
    float* sRq = sm + 20992;   // 512
    const int tid = threadIdx.x, tx = tid & 15, ty = tid >> 4;
    const int n0 = blockIdx.x * 32;

#pragma unroll
    for (int m = 0; m < 4; ++m) {
        int f4 = tid + 256 * m;
        int r = f4 >> 5, c4 = f4 & 31;
        *(float4*)(sS + r * 128 + c4 * 4) =
            *(const float4*)(g_S + (size_t)(n0 + r) * 128 + c4 * 4);
    }
#pragma unroll
    for (int m = 0; m < 16; ++m) {
        int idx = tid + 256 * m;
        int d = idx & 127, c4 = idx >> 7;
        float4 v = *(const float4*)(W3 + (size_t)d * 128 + c4 * 4);
        sW[(c4 * 4 + 0) * 128 + d] = v.x;
        sW[(c4 * 4 + 1) * 128 + d] = v.y;
        sW[(c4 * 4 + 2) * 128 + d] = v.z;
        sW[(c4 * 4 + 3) * 128 + d] = v.w;
    }
    __syncthreads();

    float acc[2][8] = {};
#pragma unroll
    for (int kk = 0; kk < 128; kk += 4) {
        float a[2][4];
#pragma unroll
        for (int i = 0; i < 2; ++i) {
            float4 t = *(float4*)(sS + (ty + 16 * i) * 128 + kk);
            a[i][0] = t.x; a[i][1] = t.y; a[i][2] = t.z; a[i][3] = t.w;
        }
#pragma unroll
        for (int q = 0; q < 4; ++q) {
            float4 b0 = *(float4*)(sW + (kk + q) * 128 + tx * 8);
            float4 b1v = *(float4*)(sW + (kk + q) * 128 + tx * 8 + 4);
            float bb[8] = {b0.x, b0.y, b0.z, b0.w, b1v.x, b1v.y, b1v.z, b1v.w};
#pragma unroll
            for (int i = 0; i < 2; ++i)
#pragma unroll
                for (int j = 0; j < 8; ++j) acc[i][j] += a[i][q] * bb[j];
        }
    }

    float xv[2][8];
    float4 b30 = *(const float4*)(b3 + tx * 8);
    float4 b31 = *(const float4*)(b3 + tx * 8 + 4);
    float b3v[8] = {b30.x, b30.y, b30.z, b30.w, b31.x, b31.y, b31.z, b31.w};
#pragma unroll
    for (int i = 0; i < 2; ++i) {
        int r = ty + 16 * i, n = n0 + r;
        float As = g_A[n];
        float4 nv0 = *(const float4*)(node + (size_t)n * 128 + tx * 8);
        float4 nv1 = *(const float4*)(node + (size_t)n * 128 + tx * 8 + 4);
        float nb[8] = {nv0.x, nv0.y, nv0.z, nv0.w, nv1.x, nv1.y, nv1.z, nv1.w};
        float s = 0.f, q = 0.f;
#pragma unroll
        for (int j = 0; j < 8; ++j) {
            float v = nb[j] + (acc[i][j] + As * b3v[j]) * (1.0f / 30.0f);
            xv[i][j] = v; s += v; q += v * v;
        }
        sRs[r * 16 + tx] = s;
        sRq[r * 16 + tx] = q;
    }
    __syncthreads();
    float4 ga = *(const float4*)(g1 + tx * 8);
    float4 gb = *(const float4*)(g1 + tx * 8 + 4);
    float4 ea = *(const float4*)(be1 + tx * 8);
    float4 ebv = *(const float4*)(be1 + tx * 8 + 4);
    float gv[8] = {ga.x, ga.y, ga.z, ga.w, gb.x, gb.y, gb.z, gb.w};
    float ev[8] = {ea.x, ea.y, ea.z, ea.w, ebv.x, ebv.y, ebv.z, ebv.w};
#pragma unroll
    for (int i = 0; i < 2; ++i) {
        int r = ty + 16 * i;
        float s = 0.f, q = 0.f;
#pragma unroll
        for (int t = 0; t < 16; ++t) { s += sRs[r * 16 + t]; q += sRq[r * 16 + t]; }
        float mu = s * (1.0f / 128.0f);
        float var = q * (1.0f / 128.0f) - mu * mu;
        float rs = rsqrtf(var + 1e-5f);
        float o[8];
#pragma unroll
        for (int j = 0; j < 8; ++j) o[j] = (xv[i][j] - mu) * rs * gv[j] + ev[j];
        *(float4*)(g_X + (size_t)(n0 + r) * 128 + tx * 8) = make_float4(o[0], o[1], o[2], o[3]);
        *(float4*)(g_X + (size_t)(n0 + r) * 128 + tx * 8 + 4) = make_float4(o[4], o[5], o[6], o[7]);
    }
}

// ================= K3: g_H = gelu(g_X @ Wd1^T + bd1)  (N=512) ===============
__global__ __launch_bounds__(256)
void k3_mlp1(const float* __restrict__ Wd1, const float* __restrict__ bd1) {
    extern __shared__ float sm[];
    float* sX = sm;          // 32*128
    float* sW = sm + 4096;   // 128*128 per n-tile: sW[k][h] = Wd1[(h0+h)*128 + k]
    const int tid = threadIdx.x, tx = tid & 15, ty = tid >> 4;
    const int n0 = blockIdx.x * 32;

#pragma unroll
    for (int m = 0; m < 4; ++m) {
        int f4 = tid + 256 * m;
        int r = f4 >> 5, c4 = f4 & 31;
        *(float4*)(sX + r * 128 + c4 * 4) =
            *(const float4*)(g_X + (size_t)(n0 + r) * 128 + c4 * 4);
    }

    for (int h0 = 0; h0 < 512; h0 += 128) {
        __syncthreads();
#pragma unroll
        for (int m = 0; m < 16; ++m) {
            int idx = tid + 256 * m;
            int h = idx & 127, k4 = idx >> 7;
            float4 v = *(const float4*)(Wd1 + (size_t)(h0 + h) * 128 + k4 * 4);
            sW[(k4 * 4 + 0) * 128 + h] = v.x;
            sW[(k4 * 4 + 1) * 128 + h] = v.y;
            sW[(k4 * 4 + 2) * 128 + h] = v.z;
            sW[(k4 * 4 + 3) * 128 + h] = v.w;
        }
        __syncthreads();
        float acc[2][8] = {};
#pragma unroll
        for (int kk = 0; kk < 128; kk += 4) {
            float a[2][4];
#pragma unroll
            for (int i = 0; i < 2; ++i) {
                float4 t = *(float4*)(sX + (ty + 16 * i) * 128 + kk);
                a[i][0] = t.x; a[i][1] = t.y; a[i][2] = t.z; a[i][3] = t.w;
            }
#pragma unroll
            for (int q = 0; q < 4; ++q) {
                float4 b0 = *(float4*)(sW + (kk + q) * 128 + tx * 8);
                float4 b1v = *(float4*)(sW + (kk + q) * 128 + tx * 8 + 4);
                float bb[8] = {b0.x, b0.y, b0.z, b0.w, b1v.x, b1v.y, b1v.z, b1v.w};
#pragma unroll
                for (int i = 0; i < 2; ++i)
#pragma unroll
                    for (int j = 0; j < 8; ++j) acc[i][j] += a[i][q] * bb[j];
            }
        }
#pragma unroll
        for (int i = 0; i < 2; ++i) {
            int r = n0 + ty + 16 * i;
#pragma unroll
            for (int j = 0; j < 8; ++j) {
                int h = h0 + tx * 8 + j;
                g_H[(size_t)r * 512 + h] = gelu_f(acc[i][j] + bd1[h]);
            }
        }
    }
}

// ===== K4: out = mask * LN2(g_X + g_H @ Wd2^T + bd2)  (K=512, N=128) ========
__global__ __launch_bounds__(256)
void k4_out(const float* __restrict__ Wd2, const float* __restrict__ bd2,
            const float* __restrict__ g2, const float* __restrict__ be2,
            const float* __restrict__ maskp, float* __restrict__ out) {
    extern __shared__ float sm[];
    float* sA = sm;            // 32*128 (k-tile of g_H)
    float* sW = sm + 4096;     // 128*128: sW[k][c] = Wd2[c*512 + k0 + k]
    float* sRs = sm + 20480;   // 512
    float* sRq = sm + 20992;   // 512
    const int tid = threadIdx.x, tx = tid & 15, ty = tid >> 4;
    const int n0 = blockIdx.x * 32;

    float acc[2][8] = {};
    for (int k0 = 0; k0 < 512; k0 += 128) {
        __syncthreads();
#pragma unroll
        for (int m = 0; m < 4; ++m) {
            int f4 = tid + 256 * m;
            int r = f4 >> 5, c4 = f4 & 31;
            *(float4*)(sA + r * 128 + c4 * 4) =
                *(const float4*)(g_H + (size_t)(n0 + r) * 512 + k0 + c4 * 4);
        }
#pragma unroll
        for (int m = 0; m < 16; ++m) {
            int idx = tid + 256 * m;
            int c = idx & 127, k4 = idx >> 7;
            float4 v = *(const float4*)(Wd2 + (size_t)c * 512 + k0 + k4 * 4);
            sW[(k4 * 4 + 0) * 128 + c] = v.x;
            sW[(k4 * 4 + 1) * 128 + c] = v.y;
            sW[(k4 * 4 + 2) * 128 + c] = v.z;
            sW[(k4 * 4 + 3) * 128 + c] = v.w;
        }
        __syncthreads();
#pragma unroll
        for (int kk = 0; kk < 128; kk += 4) {
            float a[2][4];
#pragma unroll
            for (int i = 0; i < 2; ++i) {
                float4 t = *(float4*)(sA + (ty + 16 * i) * 128 + kk);
                a[i][0] = t.x; a[i][1] = t.y; a[i][2] = t.z; a[i][3] = t.w;
            }
#pragma unroll
            for (int q = 0; q < 4; ++q) {
                float4 b0 = *(float4*)(sW + (kk + q) * 128 + tx * 8);
                float4 b1v = *(float4*)(sW + (kk + q) * 128 + tx * 8 + 4);
                float bb[8] = {b0.x, b0.y, b0.z, b0.w, b1v.x, b1v.y, b1v.z, b1v.w};
#pragma unroll
                for (int i = 0; i < 2; ++i)
#pragma unroll
                    for (int j = 0; j < 8; ++j) acc[i][j] += a[i][q] * bb[j];
            }
        }
    }

    float xv[2][8];
    float4 ba = *(const float4*)(bd2 + tx * 8);
    float4 bbv = *(const float4*)(bd2 + tx * 8 + 4);
    float bdv[8] = {ba.x, ba.y, ba.z, ba.w, bbv.x, bbv.y, bbv.z, bbv.w};
#pragma unroll
    for (int i = 0; i < 2; ++i) {
        int r = ty + 16 * i, n = n0 + r;
        float4 x0 = *(const float4*)(g_X + (size_t)n * 128 + tx * 8);
        float4 x1 = *(const float4*)(g_X + (size_t)n * 128 + tx * 8 + 4);
        float xb[8] = {x0.x, x0.y, x0.z, x0.w, x1.x, x1.y, x1.z, x1.w};
        float s = 0.f, q = 0.f;
#pragma unroll
        for (int j = 0; j < 8; ++j) {
            float v = xb[j] + acc[i][j] + bdv[j];
            xv[i][j] = v; s += v; q += v * v;
        }
        sRs[r * 16 + tx] = s;
        sRq[r * 16 + tx] = q;
    }
    __syncthreads();
    float4 ga = *(const float4*)(g2 + tx * 8);
    float4 gb = *(const float4*)(g2 + tx * 8 + 4);
    float4 ea = *(const float4*)(be2 + tx * 8);
    float4 ebv = *(const float4*)(be2 + tx * 8 + 4);
    float gv[8] = {ga.x, ga.y, ga.z, ga.w, gb.x, gb.y, gb.z, gb.w};
    float ev[8] = {ea.x, ea.y, ea.z, ea.w, ebv.x, ebv.y, ebv.z, ebv.w};
#pragma unroll
    for (int i = 0; i < 2; ++i) {
        int r = ty + 16 * i, n = n0 + r;
        float s = 0.f, q = 0.f;
#pragma unroll
        for (int t = 0; t < 16; ++t) { s += sRs[r * 16 + t]; q += sRq[r * 16 + t]; }
        float mu = s * (1.0f / 128.0f);
        float var = q * (1.0f / 128.0f) - mu * mu;
        float rs = rsqrtf(var + 1e-5f);
        float mk = maskp[n];
        float o[8];
#pragma unroll
        for (int j = 0; j < 8; ++j)
            o[j] = mk * ((xv[i][j] - mu) * rs * gv[j] + ev[j]);
        *(float4*)(out + (size_t)n * 128 + tx * 8) = make_float4(o[0], o[1], o[2], o[3]);
        *(float4*)(out + (size_t)n * 128 + tx * 8 + 4) = make_float4(o[4], o[5], o[6], o[7]);
    }
}

// ============================== launch =====================================
extern "C" void kernel_launch(void* const* d_in, const int* in_sizes, int n_in,
                              void* d_out, int out_size) {
    const float* node = (const float*)d_in[0];
    const float* edge = (const float*)d_in[1];
    const float* mask = (const float*)d_in[2];
    const float* attn = (const float*)d_in[3];
    const float* W1   = (const float*)d_in[4];
    const float* b1   = (const float*)d_in[5];
    const float* W2   = (const float*)d_in[6];
    const float* b2   = (const float*)d_in[7];
    const float* W3   = (const float*)d_in[8];
    const float* b3   = (const float*)d_in[9];
    const float* g1   = (const float*)d_in[10];
    const float* be1  = (const float*)d_in[11];
    const float* Wd1  = (const float*)d_in[12];
    const float* bd1  = (const float*)d_in[13];
    const float* Wd2  = (const float*)d_in[14];
    const float* bd2  = (const float*)d_in[15];
    const float* g2   = (const float*)d_in[16];
    const float* be2  = (const float*)d_in[17];
    float* out = (float*)d_out;

    const size_t s0 = (size_t)(4096 + 16384) * sizeof(float);
    const size_t s1 = (size_t)(16384 + 6144 + 128 + 64) * sizeof(float);
    const size_t s2 = (size_t)(4096 + 16384 + 512 + 512) * sizeof(float);
    const size_t s3 = (size_t)(4096 + 16384) * sizeof(float);
    const size_t s4 = (size_t)(4096 + 16384 + 512 + 512) * sizeof(float);

    cudaFuncSetAttribute(k0_node_pre, cudaFuncAttributeMaxDynamicSharedMemorySize, (int)s0);
    cudaFuncSetAttribute(k1_edges,    cudaFuncAttributeMaxDynamicSharedMemorySize, (int)s1);
    cudaFuncSetAttribute(k2_ln1,      cudaFuncAttributeMaxDynamicSharedMemorySize, (int)s2);
    cudaFuncSetAttribute(k3_mlp1,     cudaFuncAttributeMaxDynamicSharedMemorySize, (int)s3);
    cudaFuncSetAttribute(k4_out,      cudaFuncAttributeMaxDynamicSharedMemorySize, (int)s4);

    k0_node_pre<<<NN / 32, 256, s0>>>(node, W1, b1);
    k1_edges<<<NN, 256, s1>>>(edge, attn, W1, W2, b2);
    k2_ln1<<<NN / 32, 256, s2>>>(node, W3, b3, g1, be1);
    k3_mlp1<<<NN / 32, 256, s3>>>(Wd1, bd1);
    k4_out<<<NN / 32, 256, s4>>>(Wd2, bd2, g2, be2, mask, out);
}

// round 3
// speedup vs baseline: 1.0586x; 1.0586x over previous
#include <cuda_runtime.h>
#include <math.h>

#define NN 4096
#define KN 48
#define CC 128
#define EC 384
#define HD 512

// ---------------- scratch (device globals: allocation-free) ----------------
__device__ float g_node_pre[NN * CC];   // node @ W1a^T + b_m1
__device__ float g_S[NN * CC];          // sum_k attn * h2
__device__ float g_A[NN];               // sum_k attn
__device__ float g_X[NN * CC];          // post-LN1 x
__device__ float g_H[NN * HD];          // gelu(x @ Wd1^T + bd1)

__device__ __forceinline__ float gelu_f(float x) {
    return 0.5f * x * (1.0f + erff(x * 0.70710678118654752440f));
}

// ======================= K0: node_pre = node @ W1a^T + b1 ==================
// M=4096 (32 rows/block), N=128, K=128
__global__ __launch_bounds__(256)
void k0_node_pre(const float* __restrict__ node, const float* __restrict__ W1,
                 const float* __restrict__ b1) {
    extern __shared__ float sm[];
    float* sX = sm;           // 32*128
    float* sW = sm + 4096;    // 128*128  sW[k][c] = W1[c*512 + k]
    const int tid = threadIdx.x, tx = tid & 15, ty = tid >> 4;
    const int n0 = blockIdx.x * 32;

#pragma unroll
    for (int m = 0; m < 4; ++m) {
        int f4 = tid + 256 * m;              // 0..1023
        int r = f4 >> 5, c4 = f4 & 31;
        *(float4*)(sX + r * 128 + c4 * 4) =
            *(const float4*)(node + (size_t)(n0 + r) * 128 + c4 * 4);
    }
#pragma unroll
    for (int m = 0; m < 16; ++m) {
        int idx = tid + 256 * m;             // 0..4095
        int c = idx & 127, k4 = idx >> 7;
        float4 v = *(const float4*)(W1 + (size_t)c * 512 + k4 * 4);
        sW[(k4 * 4 + 0) * 128 + c] = v.x;
        sW[(k4 * 4 + 1) * 128 + c] = v.y;
        sW[(k4 * 4 + 2) * 128 + c] = v.z;
        sW[(k4 * 4 + 3) * 128 + c] = v.w;
    }
    __syncthreads();

    float acc[2][8] = {};
#pragma unroll
    for (int kk = 0; kk < 128; kk += 4) {
        float a[2][4];
#pragma unroll
        for (int i = 0; i < 2; ++i) {
            float4 t = *(float4*)(sX + (ty + 16 * i) * 128 + kk);
            a[i][0] = t.x; a[i][1] = t.y; a[i][2] = t.z; a[i][3] = t.w;
        }
#pragma unroll
        for (int q = 0; q < 4; ++q) {
            float4 b0 = *(float4*)(sW + (kk + q) * 128 + tx * 8);
            float4 b1v = *(float4*)(sW + (kk + q) * 128 + tx * 8 + 4);
            float bb[8] = {b0.x, b0.y, b0.z, b0.w, b1v.x, b1v.y, b1v.z, b1v.w};
#pragma unroll
            for (int i = 0; i < 2; ++i)
#pragma unroll
                for (int j = 0; j < 8; ++j) acc[i][j] += a[i][q] * bb[j];
        }
    }
#pragma unroll
    for (int i = 0; i < 2; ++i) {
        int r = n0 + ty + 16 * i;
#pragma unroll
        for (int j = 0; j < 8; ++j) {
            int c = tx * 8 + j;
            g_node_pre[(size_t)r * 128 + c] = acc[i][j] + b1[c];
        }
    }
}

// ======================= K1: per-node edge message kernel ===================
// block = one node n. GEMM1b (48x384 @ 384x128) + gelu, GEMM2 (48x128 @ 128x128)
// + gelu, attn-weighted reduce over 48 -> g_S, g_A.
__global__ __launch_bounds__(256, 2)
void k1_edges(const float* __restrict__ edge, const float* __restrict__ attn,
              const float* __restrict__ W1, const float* __restrict__ W2,
              const float* __restrict__ b2) {
    extern __shared__ float sm[];
    float* sU = sm;                 // 16384 floats: union{sA,sB} / sB2
    float* sH = sm + 16384;         // 6144: h1 (48x128), later sPart
    float* sNP = sm + 16384 + 6144; // 128
    float* sAt = sNP + 128;         // 64 (48 used)
    float* sA = sU;                 // 48*64
    float* sB = sU + 3072;          // 64*128

    const int n = blockIdx.x;
    const int tid = threadIdx.x;
    const int tx = tid & 15;
    const int ty = tid >> 4;
    const float* eb = edge + (size_t)n * (KN * EC);

    if (tid < 128) sNP[tid] = g_node_pre[(size_t)n * 128 + tid];
    if (tid < KN) sAt[tid] = attn[(size_t)n * KN + tid];

    float acc[3][8] = {};

    // ---- GEMM1b over edge context, k-tiles of 64 ----
    for (int kt = 0; kt < 6; ++kt) {
        __syncthreads();
#pragma unroll
        for (int m = 0; m < 3; ++m) {
            int f4 = tid + 256 * m;          // 0..767
            int r = f4 >> 4, c4 = f4 & 15;
            *(float4*)(sA + r * 64 + c4 * 4) =
                *(const float4*)(eb + (size_t)r * EC + kt * 64 + c4 * 4);
        }
#pragma unroll
        for (int m = 0; m < 8; ++m) {
            int idx = tid + 256 * m;         // 0..2047
            int c = idx & 127, d4 = idx >> 7;
            float4 v = *(const float4*)(W1 + (size_t)c * 512 + 128 + kt * 64 + d4 * 4);
            sB[(d4 * 4 + 0) * 128 + c] = v.x;
            sB[(d4 * 4 + 1) * 128 + c] = v.y;
            sB[(d4 * 4 + 2) * 128 + c] = v.z;
            sB[(d4 * 4 + 3) * 128 + c] = v.w;
        }
        __syncthreads();
#pragma unroll
        for (int kk = 0; kk < 64; kk += 4) {
            float a[3][4];
#pragma unroll
            for (int i = 0; i < 3; ++i) {
                float4 t = *(float4*)(sA + (ty + 16 * i) * 64 + kk);
                a[i][0] = t.x; a[i][1] = t.y; a[i][2] = t.z; a[i][3] = t.w;
            }
#pragma unroll
            for (int q = 0; q < 4; ++q) {
                float4 b0 = *(float4*)(sB + (kk + q) * 128 + tx * 8);
                float4 b1v = *(float4*)(sB + (kk + q) * 128 + tx * 8 + 4);
                float bb[8] = {b0.x, b0.y, b0.z, b0.w, b1v.x, b1v.y, b1v.z, b1v.w};
#pragma unroll
                for (int i = 0; i < 3; ++i)
#pragma unroll
                    for (int j = 0; j < 8; ++j) acc[i][j] += a[i][q] * bb[j];
            }
        }
    }

    // ---- epilogue 1: h1 = gelu(node_pre + acc) -> sH ----
#pragma unroll
    for (int i = 0; i < 3; ++i) {
        int r = ty + 16 * i;
        float h[8];
#pragma unroll
        for (int j = 0; j < 8; ++j) h[j] = gelu_f(acc[i][j] + sNP[tx * 8 + j]);
        *(float4*)(sH + r * 128 + tx * 8) = make_float4(h[0], h[1], h[2], h[3]);
        *(float4*)(sH + r * 128 + tx * 8 + 4) = make_float4(h[4], h[5], h[6], h[7]);
    }
    __syncthreads();

    // ---- load W2^T into sU: sU[c][d] = W2[d*128 + c] ----
#pragma unroll
    for (int m = 0; m < 16; ++m) {
        int idx = tid + 256 * m;             // 0..4095
        int d = idx & 127, c4 = idx >> 7;
        float4 v = *(const float4*)(W2 + (size_t)d * 128 + c4 * 4);
        sU[(c4 * 4 + 0) * 128 + d] = v.x;
        sU[(c4 * 4 + 1) * 128 + d] = v.y;
        sU[(c4 * 4 + 2) * 128 + d] = v.z;
        sU[(c4 * 4 + 3) * 128 + d] = v.w;
    }
    __syncthreads();

    // ---- GEMM2: acc2 = h1 @ W2^T ----
    float acc2[3][8] = {};
#pragma unroll
    for (int kk = 0; kk < 128; kk += 4) {
        float a[3][4];
#pragma unroll
        for (int i = 0; i < 3; ++i) {
            float4 t = *(float4*)(sH + (ty + 16 * i) * 128 + kk);
            a[i][0] = t.x; a[i][1] = t.y; a[i][2] = t.z; a[i][3] = t.w;
        }
#pragma unroll
        for (int q = 0; q < 4; ++q) {
            float4 b0 = *(float4*)(sU + (kk + q) * 128 + tx * 8);
            float4 b1v = *(float4*)(sU + (kk + q) * 128 + tx * 8 + 4);
            float bb[8] = {b0.x, b0.y, b0.z, b0.w, b1v.x, b1v.y, b1v.z, b1v.w};
#pragma unroll
            for (int i = 0; i < 3; ++i)
#pragma unroll
                for (int j = 0; j < 8; ++j) acc2[i][j] += a[i][q] * bb[j];
        }
    }

    // ---- epilogue 2: h2 = gelu(acc2 + b2); weighted partial over rows ----
    float w0 = sAt[ty], w1 = sAt[ty + 16], w2 = sAt[ty + 32];
    float4 b2a = *(const float4*)(b2 + tx * 8);
    float4 b2b = *(const float4*)(b2 + tx * 8 + 4);
    float b2v[8] = {b2a.x, b2a.y, b2a.z, b2a.w, b2b.x, b2b.y, b2b.z, b2b.w};
    float part[8];
#pragma unroll
    for (int j = 0; j < 8; ++j) {
        float p0 = gelu_f(acc2[0][j] + b2v[j]);
        float p1 = gelu_f(acc2[1][j] + b2v[j]);
        float p2 = gelu_f(acc2[2][j] + b2v[j]);
        part[j] = w0 * p0 + w1 * p1 + w2 * p2;
    }
    __syncthreads();                 // all sH reads done -> reuse as sPart
    float* sPart = sH;               // 16 x 128
    *(float4*)(sPart + ty * 128 + tx * 8) = make_float4(part[0], part[1], part[2], part[3]);
    *(float4*)(sPart + ty * 128 + tx * 8 + 4) = make_float4(part[4], part[5], part[6], part[7]);
    __syncthreads();

    if (tid < 128) {
        float s = 0.f;
#pragma unroll
        for (int t = 0; t < 16; ++t) s += sPart[t * 128 + tid];
        g_S[(size_t)n * 128 + tid] = s;
    }
    if (tid == 0) {
        float s = 0.f;
#pragma unroll
        for (int k = 0; k < KN; ++k) s += sAt[k];
        g_A[n] = s;
    }
}

// ========= K2: x = LN1(node + (W3 @ S + A*b3)/30) -> g_X (fused) ===========
__global__ __launch_bounds__(256)
void k2_ln1(const float* __restrict__ node, const float* __restrict__ W3,
            const float* __restrict__ b3, const float* __restrict__ g1,
            const float* __restrict__ be1) {
    extern __shared__ float sm[];
    float* sS = sm;            // 32*128
    float* sW = sm + 4096;     // 128*128  sW[c][d] = W3[d*128 + c]
    float* sRs = sm + 20480;   // 512
    float* sRq = sm + 20992;   // 512
    const int tid = threadIdx.x, tx = tid & 15, ty = tid >> 4;
    const int n0 = blockIdx.x * 32;

#pragma unroll
    for (int m = 0; m < 4; ++m) {
        int f4 = tid + 256 * m;
        int r = f4 >> 5, c4 = f4 & 31;
        *(float4*)(sS + r * 128 + c4 * 4) =
            *(const float4*)(g_S + (size_t)(n0 + r) * 128 + c4 * 4);
    }
#pragma unroll
    for (int m = 0; m < 16; ++m) {
        int idx = tid + 256 * m;
        int d = idx & 127, c4 = idx >> 7;
        float4 v = *(const float4*)(W3 + (size_t)d * 128 + c4 * 4);
        sW[(c4 * 4 + 0) * 128 + d] = v.x;
        sW[(c4 * 4 + 1) * 128 + d] = v.y;
        sW[(c4 * 4 + 2) * 128 + d] = v.z;
        sW[(c4 * 4 + 3) * 128 + d] = v.w;
    }
    __syncthreads();

    float acc[2][8] = {};
#pragma unroll
    for (int kk = 0; kk < 128; kk += 4) {
        float a[2][4];
#pragma unroll
        for (int i = 0; i < 2; ++i) {
            float4 t = *(float4*)(sS + (ty + 16 * i) * 128 + kk);
            a[i][0] = t.x; a[i][1] = t.y; a[i][2] = t.z; a[i][3] = t.w;
        }
#pragma unroll
        for (int q = 0; q < 4; ++q) {
            float4 b0 = *(float4*)(sW + (kk + q) * 128 + tx * 8);
            float4 b1v = *(float4*)(sW + (kk + q) * 128 + tx * 8 + 4);
            float bb[8] = {b0.x, b0.y, b0.z, b0.w, b1v.x, b1v.y, b1v.z, b1v.w};
#pragma unroll
            for (int i = 0; i < 2; ++i)
#pragma unroll
                for (int j = 0; j < 8; ++j) acc[i][j] += a[i][q] * bb[j];
        }
    }

    float xv[2][8];
    float4 b30 = *(const float4*)(b3 + tx * 8);
    float4 b31 = *(const float4*)(b3 + tx * 8 + 4);
    float b3v[8] = {b30.x, b30.y, b30.z, b30.w, b31.x, b31.y, b31.z, b31.w};
#pragma unroll
    for (int i = 0; i < 2; ++i) {
        int r = ty + 16 * i, n = n0 + r;
        float As = g_A[n];
        float4 nv0 = *(const float4*)(node + (size_t)n * 128 + tx * 8);
        float4 nv1 = *(const float4*)(node + (size_t)n * 128 + tx * 8 + 4);
        float nb[8] = {nv0.x, nv0.y, nv0.z, nv0.w, nv1.x, nv1.y, nv1.z, nv1.w};
        float s = 0.f, q = 0.f;
#pragma unroll
        for (int j = 0; j < 8; ++j) {
            float v = nb[j] + (acc[i][j] + As * b3v[j]) * (1.0f / 30.0f);
            xv[i][j] = v; s += v; q += v * v;
        }
        sRs[r * 16 + tx] = s;
        sRq[r * 16 + tx] = q;
    }
    __syncthreads();
    float4 ga = *(const float4*)(g1 + tx * 8);
    float4 gb = *(const float4*)(g1 + tx * 8 + 4);
    float4 ea = *(const float4*)(be1 + tx * 8);
    float4 ebv = *(const float4*)(be1 + tx * 8 + 4);
    float gv[8] = {ga.x, ga.y, ga.z, ga.w, gb.x, gb.y, gb.z, gb.w};
    float ev[8] = {ea.x, ea.y, ea.z, ea.w, ebv.x, ebv.y, ebv.z, ebv.w};
#pragma unroll
    for (int i = 0; i < 2; ++i) {
        int r = ty + 16 * i;
        float s = 0.f, q = 0.f;
#pragma unroll
        for (int t = 0; t < 16; ++t) { s += sRs[r * 16 + t]; q += sRq[r * 16 + t]; }
        float mu = s * (1.0f / 128.0f);
        float var = q * (1.0f / 128.0f) - mu * mu;
        float rs = rsqrtf(var + 1e-5f);
        float o[8];
#pragma unroll
        for (int j = 0; j < 8; ++j) o[j] = (xv[i][j] - mu) * rs * gv[j] + ev[j];
        *(float4*)(g_X + (size_t)(n0 + r) * 128 + tx * 8) = make_float4(o[0], o[1], o[2], o[3]);
        *(float4*)(g_X + (size_t)(n0 + r) * 128 + tx * 8 + 4) = make_float4(o[4], o[5], o[6], o[7]);
    }
}

// ================= K3: g_H = gelu(g_X @ Wd1^T + bd1)  (N=512) ===============
__global__ __launch_bounds__(256)
void k3_mlp1(const float* __restrict__ Wd1, const float* __restrict__ bd1) {
    extern __shared__ float sm[];
    float* sX = sm;          // 32*128
    float* sW = sm + 4096;   // 128*128 per n-tile: sW[k][h] = Wd1[(h0+h)*128 + k]
    const int tid = threadIdx.x, tx = tid & 15, ty = tid >> 4;
    const int n0 = blockIdx.x * 32;

#pragma unroll
    for (int m = 0; m < 4; ++m) {
        int f4 = tid + 256 * m;
        int r = f4 >> 5, c4 = f4 & 31;
        *(float4*)(sX + r * 128 + c4 * 4) =
            *(const float4*)(g_X + (size_t)(n0 + r) * 128 + c4 * 4);
    }

    for (int h0 = 0; h0 < 512; h0 += 128) {
        __syncthreads();
#pragma unroll
        for (int m = 0; m < 16; ++m) {
            int idx = tid + 256 * m;
            int h = idx & 127, k4 = idx >> 7;
            float4 v = *(const float4*)(Wd1 + (size_t)(h0 + h) * 128 + k4 * 4);
            sW[(k4 * 4 + 0) * 128 + h] = v.x;
            sW[(k4 * 4 + 1) * 128 + h] = v.y;
            sW[(k4 * 4 + 2) * 128 + h] = v.z;
            sW[(k4 * 4 + 3) * 128 + h] = v.w;
        }
        __syncthreads();
        float acc[2][8] = {};
#pragma unroll
        for (int kk = 0; kk < 128; kk += 4) {
            float a[2][4];
#pragma unroll
            for (int i = 0; i < 2; ++i) {
                float4 t = *(float4*)(sX + (ty + 16 * i) * 128 + kk);
                a[i][0] = t.x; a[i][1] = t.y; a[i][2] = t.z; a[i][3] = t.w;
            }
#pragma unroll
            for (int q = 0; q < 4; ++q) {
                float4 b0 = *(float4*)(sW + (kk + q) * 128 + tx * 8);
                float4 b1v = *(float4*)(sW + (kk + q) * 128 + tx * 8 + 4);
                float bb[8] = {b0.x, b0.y, b0.z, b0.w, b1v.x, b1v.y, b1v.z, b1v.w};
#pragma unroll
                for (int i = 0; i < 2; ++i)
#pragma unroll
                    for (int j = 0; j < 8; ++j) acc[i][j] += a[i][q] * bb[j];
            }
        }
#pragma unroll
        for (int i = 0; i < 2; ++i) {
            int r = n0 + ty + 16 * i;
#pragma unroll
            for (int j = 0; j < 8; ++j) {
                int h = h0 + tx * 8 + j;
                g_H[(size_t)r * 512 + h] = gelu_f(acc[i][j] + bd1[h]);
            }
        }
    }
}

// ===== K4: out = mask * LN2(g_X + g_H @ Wd2^T + bd2)  (K=512, N=128) ========
__global__ __launch_bounds__(256)
void k4_out(const float* __restrict__ Wd2, const float* __restrict__ bd2,
            const float* __restrict__ g2, const float* __restrict__ be2,
            const float* __restrict__ maskp, float* __restrict__ out) {
    extern __shared__ float sm[];
    float* sA = sm;            // 32*128 (k-tile of g_H)
    float* sW = sm + 4096;     // 128*128: sW[k][c] = Wd2[c*512 + k0 + k]
    float* sRs = sm + 20480;   // 512
    float* sRq = sm + 20992;   // 512
    const int tid = threadIdx.x, tx = tid & 15, ty = tid >> 4;
    const int n0 = blockIdx.x * 32;

    float acc[2][8] = {};
    for (int k0 = 0; k0 < 512; k0 += 128) {
        __syncthreads();
#pragma unroll
        for (int m = 0; m < 4; ++m) {
            int f4 = tid + 256 * m;
            int r = f4 >> 5, c4 = f4 & 31;
            *(float4*)(sA + r * 128 + c4 * 4) =
                *(const float4*)(g_H + (size_t)(n0 + r) * 512 + k0 + c4 * 4);
        }
#pragma unroll
        for (int m = 0; m < 16; ++m) {
            int idx = tid + 256 * m;
            int c = idx & 127, k4 = idx >> 7;
            float4 v = *(const float4*)(Wd2 + (size_t)c * 512 + k0 + k4 * 4);
            sW[(k4 * 4 + 0) * 128 + c] = v.x;
            sW[(k4 * 4 + 1) * 128 + c] = v.y;
            sW[(k4 * 4 + 2) * 128 + c] = v.z;
            sW[(k4 * 4 + 3) * 128 + c] = v.w;
        }
        __syncthreads();
#pragma unroll
        for (int kk = 0; kk < 128; kk += 4) {
            float a[2][4];
#pragma unroll
            for (int i = 0; i < 2; ++i) {
                float4 t = *(float4*)(sA + (ty + 16 * i) * 128 + kk);
                a[i][0] = t.x; a[i][1] = t.y; a[i][2] = t.z; a[i][3] = t.w;
            }
#pragma unroll
            for (int q = 0; q < 4; ++q) {
                float4 b0 = *(float4*)(sW + (kk + q) * 128 + tx * 8);
                float4 b1v = *(float4*)(sW + (kk + q) * 128 + tx * 8 + 4);
                float bb[8] = {b0.x, b0.y, b0.z, b0.w, b1v.x, b1v.y, b1v.z, b1v.w};
#pragma unroll
                for (int i = 0; i < 2; ++i)
#pragma unroll
                    for (int j = 0; j < 8; ++j) acc[i][j] += a[i][q] * bb[j];
            }
        }
    }

    float xv[2][8];
    float4 ba = *(const float4*)(bd2 + tx * 8);
    float4 bbv = *(const float4*)(bd2 + tx * 8 + 4);
    float bdv[8] = {ba.x, ba.y, ba.z, ba.w, bbv.x, bbv.y, bbv.z, bbv.w};
#pragma unroll
    for (int i = 0; i < 2; ++i) {
        int r = ty + 16 * i, n = n0 + r;
        float4 x0 = *(const float4*)(g_X + (size_t)n * 128 + tx * 8);
        float4 x1 = *(const float4*)(g_X + (size_t)n * 128 + tx * 8 + 4);
        float xb[8] = {x0.x, x0.y, x0.z, x0.w, x1.x, x1.y, x1.z, x1.w};
        float s = 0.f, q = 0.f;
#pragma unroll
        for (int j = 0; j < 8; ++j) {
            float v = xb[j] + acc[i][j] + bdv[j];
            xv[i][j] = v; s += v; q += v * v;
        }
        sRs[r * 16 + tx] = s;
        sRq[r * 16 + tx] = q;
    }
    __syncthreads();
    float4 ga = *(const float4*)(g2 + tx * 8);
    float4 gb = *(const float4*)(g2 + tx * 8 + 4);
    float4 ea = *(const float4*)(be2 + tx * 8);
    float4 ebv = *(const float4*)(be2 + tx * 8 + 4);
    float gv[8] = {ga.x, ga.y, ga.z, ga.w, gb.x, gb.y, gb.z, gb.w};
    float ev[8] = {ea.x, ea.y, ea.z, ea.w, ebv.x, ebv.y, ebv.z, ebv.w};
#pragma unroll
    for (int i = 0; i < 2; ++i) {
        int r = ty + 16 * i, n = n0 + r;
        float s = 0.f, q = 0.f;
#pragma unroll
        for (int t = 0; t < 16; ++t) { s += sRs[r * 16 + t]; q += sRq[r * 16 + t]; }
        float mu = s * (1.0f / 128.0f);
        float var = q * (1.0f / 128.0f) - mu * mu;
        float rs = rsqrtf(var + 1e-5f);
        float mk = maskp[n];
        float o[8];
#pragma unroll
        for (int j = 0; j < 8; ++j)
            o[j] = mk * ((xv[i][j] - mu) * rs * gv[j] + ev[j]);
        *(float4*)(out + (size_t)n * 128 + tx * 8) = make_float4(o[0], o[1], o[2], o[3]);
        *(float4*)(out + (size_t)n * 128 + tx * 8 + 4) = make_float4(o[4], o[5], o[6], o[7]);
    }
}

// ============================== launch =====================================
extern "C" void kernel_launch(void* const* d_in, const int* in_sizes, int n_in,
                              void* d_out, int out_size) {
    const float* node = (const float*)d_in[0];
    const float* edge = (const float*)d_in[1];
    const float* mask = (const float*)d_in[2];
    const float* attn = (const float*)d_in[3];
    const float* W1   = (const float*)d_in[4];
    const float* b1   = (const float*)d_in[5];
    const float* W2   = (const float*)d_in[6];
    const float* b2   = (const float*)d_in[7];
    const float* W3   = (const float*)d_in[8];
    const float* b3   = (const float*)d_in[9];
    const float* g1   = (const float*)d_in[10];
    const float* be1  = (const float*)d_in[11];
    const float* Wd1  = (const float*)d_in[12];
    const float* bd1  = (const float*)d_in[13];
    const float* Wd2  = (const float*)d_in[14];
    const float* bd2  = (const float*)d_in[15];
    const float* g2   = (const float*)d_in[16];
    const float* be2  = (const float*)d_in[17];
    float* out = (float*)d_out;

    const size_t s0 = (size_t)(4096 + 16384) * sizeof(float);
    const size_t s1 = (size_t)(16384 + 6144 + 128 + 64) * sizeof(float);
    const size_t s2 = (size_t)(4096 + 16384 + 512 + 512) * sizeof(float);
    const size_t s3 = (size_t)(4096 + 16384) * sizeof(float);
    const size_t s4 = (size_t)(4096 + 16384 + 512 + 512) * sizeof(float);

    cudaFuncSetAttribute(k0_node_pre, cudaFuncAttributeMaxDynamicSharedMemorySize, (int)s0);
    cudaFuncSetAttribute(k1_edges,    cudaFuncAttributeMaxDynamicSharedMemorySize, (int)s1);
    cudaFuncSetAttribute(k2_ln1,      cudaFuncAttributeMaxDynamicSharedMemorySize, (int)s2);
    cudaFuncSetAttribute(k3_mlp1,     cudaFuncAttributeMaxDynamicSharedMemorySize, (int)s3);
    cudaFuncSetAttribute(k4_out,      cudaFuncAttributeMaxDynamicSharedMemorySize, (int)s4);

    k0_node_pre<<<NN / 32, 256, s0>>>(node, W1, b1);
    k1_edges<<<NN, 256, s1>>>(edge, attn, W1, W2, b2);
    k2_ln1<<<NN / 32, 256, s2>>>(node, W3, b3, g1, be1);
    k3_mlp1<<<NN / 32, 256, s3>>>(Wd1, bd1);
    k4_out<<<NN / 32, 256, s4>>>(Wd2, bd2, g2, be2, mask, out);
}

// round 4
// speedup vs baseline: 1.0588x; 1.0002x over previous
#include <cuda_runtime.h>
#include <math.h>

#define NN 4096
#define KN 48
#define CC 128
#define EC 384
#define HD 512

// ---------------- scratch (device globals: allocation-free) ----------------
__device__ float g_node_pre[NN * CC];   // node @ W1a^T + b_m1
__device__ float g_S[NN * CC];          // sum_k attn * h2
__device__ float g_A[NN];               // sum_k attn
__device__ float g_X[NN * CC];          // post-LN1 x
__device__ float g_H[NN * HD];          // gelu(x @ Wd1^T + bd1)

__device__ __forceinline__ float gelu_f(float x) {
    return 0.5f * x * (1.0f + erff(x * 0.70710678118654752440f));
}

// ======================= K0: node_pre = node @ W1a^T + b1 ==================
// M=4096 (32 rows/block), N=128, K=128
__global__ __launch_bounds__(256)
void k0_node_pre(const float* __restrict__ node, const float* __restrict__ W1,
                 const float* __restrict__ b1) {
    extern __shared__ float sm[];
    float* sX = sm;           // 32*128
    float* sW = sm + 4096;    // 128*128  sW[k][c] = W1[c*512 + k]
    const int tid = threadIdx.x, tx = tid & 15, ty = tid >> 4;
    const int n0 = blockIdx.x * 32;

#pragma unroll
    for (int m = 0; m < 4; ++m) {
        int f4 = tid + 256 * m;              // 0..1023
        int r = f4 >> 5, c4 = f4 & 31;
        *(float4*)(sX + r * 128 + c4 * 4) =
            *(const float4*)(node + (size_t)(n0 + r) * 128 + c4 * 4);
    }
#pragma unroll
    for (int m = 0; m < 16; ++m) {
        int idx = tid + 256 * m;             // 0..4095
        int c = idx & 127, k4 = idx >> 7;
        float4 v = *(const float4*)(W1 + (size_t)c * 512 + k4 * 4);
        sW[(k4 * 4 + 0) * 128 + c] = v.x;
        sW[(k4 * 4 + 1) * 128 + c] = v.y;
        sW[(k4 * 4 + 2) * 128 + c] = v.z;
        sW[(k4 * 4 + 3) * 128 + c] = v.w;
    }
    __syncthreads();

    float acc[2][8] = {};
#pragma unroll
    for (int kk = 0; kk < 128; kk += 4) {
        float a[2][4];
#pragma unroll
        for (int i = 0; i < 2; ++i) {
            float4 t = *(float4*)(sX + (ty + 16 * i) * 128 + kk);
            a[i][0] = t.x; a[i][1] = t.y; a[i][2] = t.z; a[i][3] = t.w;
        }
#pragma unroll
        for (int q = 0; q < 4; ++q) {
            float4 b0 = *(float4*)(sW + (kk + q) * 128 + tx * 8);
            float4 b1v = *(float4*)(sW + (kk + q) * 128 + tx * 8 + 4);
            float bb[8] = {b0.x, b0.y, b0.z, b0.w, b1v.x, b1v.y, b1v.z, b1v.w};
#pragma unroll
            for (int i = 0; i < 2; ++i)
#pragma unroll
                for (int j = 0; j < 8; ++j) acc[i][j] += a[i][q] * bb[j];
        }
    }
#pragma unroll
    for (int i = 0; i < 2; ++i) {
        int r = n0 + ty + 16 * i;
#pragma unroll
        for (int j = 0; j < 8; ++j) {
            int c = tx * 8 + j;
            g_node_pre[(size_t)r * 128 + c] = acc[i][j] + b1[c];
        }
    }
}

// ======================= K1: per-node edge message kernel ===================
// block = one node n. GEMM1b (48x384 @ 384x128) + gelu, GEMM2 (48x128 @ 128x128)
// + gelu, attn-weighted reduce over 48 -> g_S, g_A.
__global__ __launch_bounds__(256, 2)
void k1_edges(const float* __restrict__ edge, const float* __restrict__ attn,
              const float* __restrict__ W1, const float* __restrict__ W2,
              const float* __restrict__ b2) {
    extern __shared__ float sm[];
    float* sU = sm;                 // 16384 floats: union{sA,sB} / sB2
    float* sH = sm + 16384;         // 6144: h1 (48x128), later sPart
    float* sNP = sm + 16384 + 6144; // 128
    float* sAt = sNP + 128;         // 64 (48 used)
    float* sA = sU;                 // 48*64
    float* sB = sU + 3072;          // 64*128

    const int n = blockIdx.x;
    const int tid = threadIdx.x;
    const int tx = tid & 15;
    const int ty = tid >> 4;
    const float* eb = edge + (size_t)n * (KN * EC);

    if (tid < 128) sNP[tid] = g_node_pre[(size_t)n * 128 + tid];
    if (tid < KN) sAt[tid] = attn[(size_t)n * KN + tid];

    float acc[3][8] = {};

    // ---- GEMM1b over edge context, k-tiles of 64 ----
    for (int kt = 0; kt < 6; ++kt) {
        __syncthreads();
#pragma unroll
        for (int m = 0; m < 3; ++m) {
            int f4 = tid + 256 * m;          // 0..767
            int r = f4 >> 4, c4 = f4 & 15;
            *(float4*)(sA + r * 64 + c4 * 4) =
                *(const float4*)(eb + (size_t)r * EC + kt * 64 + c4 * 4);
        }
#pragma unroll
        for (int m = 0; m < 8; ++m) {
            int idx = tid + 256 * m;         // 0..2047
            int c = idx & 127, d4 = idx >> 7;
            float4 v = *(const float4*)(W1 + (size_t)c * 512 + 128 + kt * 64 + d4 * 4);
            sB[(d4 * 4 + 0) * 128 + c] = v.x;
            sB[(d4 * 4 + 1) * 128 + c] = v.y;
            sB[(d4 * 4 + 2) * 128 + c] = v.z;
            sB[(d4 * 4 + 3) * 128 + c] = v.w;
        }
        __syncthreads();
#pragma unroll
        for (int kk = 0; kk < 64; kk += 4) {
            float a[3][4];
#pragma unroll
            for (int i = 0; i < 3; ++i) {
                float4 t = *(float4*)(sA + (ty + 16 * i) * 64 + kk);
                a[i][0] = t.x; a[i][1] = t.y; a[i][2] = t.z; a[i][3] = t.w;
            }
#pragma unroll
            for (int q = 0; q < 4; ++q) {
                float4 b0 = *(float4*)(sB + (kk + q) * 128 + tx * 8);
                float4 b1v = *(float4*)(sB + (kk + q) * 128 + tx * 8 + 4);
                float bb[8] = {b0.x, b0.y, b0.z, b0.w, b1v.x, b1v.y, b1v.z, b1v.w};
#pragma unroll
                for (int i = 0; i < 3; ++i)
#pragma unroll
                    for (int j = 0; j < 8; ++j) acc[i][j] += a[i][q] * bb[j];
            }
        }
    }

    // ---- epilogue 1: h1 = gelu(node_pre + acc) -> sH ----
#pragma unroll
    for (int i = 0; i < 3; ++i) {
        int r = ty + 16 * i;
        float h[8];
#pragma unroll
        for (int j = 0; j < 8; ++j) h[j] = gelu_f(acc[i][j] + sNP[tx * 8 + j]);
        *(float4*)(sH + r * 128 + tx * 8) = make_float4(h[0], h[1], h[2], h[3]);
        *(float4*)(sH + r * 128 + tx * 8 + 4) = make_float4(h[4], h[5], h[6], h[7]);
    }
    __syncthreads();

    // ---- load W2^T into sU: sU[c][d] = W2[d*128 + c] ----
#pragma unroll
    for (int m = 0; m < 16; ++m) {
        int idx = tid + 256 * m;             // 0..4095
        int d = idx & 127, c4 = idx >> 7;
        float4 v = *(const float4*)(W2 + (size_t)d * 128 + c4 * 4);
        sU[(c4 * 4 + 0) * 128 + d] = v.x;
        sU[(c4 * 4 + 1) * 128 + d] = v.y;
        sU[(c4 * 4 + 2) * 128 + d] = v.z;
        sU[(c4 * 4 + 3) * 128 + d] = v.w;
    }
    __syncthreads();

    // ---- GEMM2: acc2 = h1 @ W2^T ----
    float acc2[3][8] = {};
#pragma unroll
    for (int kk = 0; kk < 128; kk += 4) {
        float a[3][4];
#pragma unroll
        for (int i = 0; i < 3; ++i) {
            float4 t = *(float4*)(sH + (ty + 16 * i) * 128 + kk);
            a[i][0] = t.x; a[i][1] = t.y; a[i][2] = t.z; a[i][3] = t.w;
        }
#pragma unroll
        for (int q = 0; q < 4; ++q) {
            float4 b0 = *(float4*)(sU + (kk + q) * 128 + tx * 8);
            float4 b1v = *(float4*)(sU + (kk + q) * 128 + tx * 8 + 4);
            float bb[8] = {b0.x, b0.y, b0.z, b0.w, b1v.x, b1v.y, b1v.z, b1v.w};
#pragma unroll
            for (int i = 0; i < 3; ++i)
#pragma unroll
                for (int j = 0; j < 8; ++j) acc2[i][j] += a[i][q] * bb[j];
        }
    }

    // ---- epilogue 2: h2 = gelu(acc2 + b2); weighted partial over rows ----
    float w0 = sAt[ty], w1 = sAt[ty + 16], w2 = sAt[ty + 32];
    float4 b2a = *(const float4*)(b2 + tx * 8);
    float4 b2b = *(const float4*)(b2 + tx * 8 + 4);
    float b2v[8] = {b2a.x, b2a.y, b2a.z, b2a.w, b2b.x, b2b.y, b2b.z, b2b.w};
    float part[8];
#pragma unroll
    for (int j = 0; j < 8; ++j) {
        float p0 = gelu_f(acc2[0][j] + b2v[j]);
        float p1 = gelu_f(acc2[1][j] + b2v[j]);
        float p2 = gelu_f(acc2[2][j] + b2v[j]);
        part[j] = w0 * p0 + w1 * p1 + w2 * p2;
    }
    __syncthreads();                 // all sH reads done -> reuse as sPart
    float* sPart = sH;               // 16 x 128
    *(float4*)(sPart + ty * 128 + tx * 8) = make_float4(part[0], part[1], part[2], part[3]);
    *(float4*)(sPart + ty * 128 + tx * 8 + 4) = make_float4(part[4], part[5], part[6], part[7]);
    __syncthreads();

    if (tid < 128) {
        float s = 0.f;
#pragma unroll
        for (int t = 0; t < 16; ++t) s += sPart[t * 128 + tid];
        g_S[(size_t)n * 128 + tid] = s;
    }
    if (tid == 0) {
        float s = 0.f;
#pragma unroll
        for (int k = 0; k < KN; ++k) s += sAt[k];
        g_A[n] = s;
    }
}

// ========= K2: x = LN1(node + (W3 @ S + A*b3)/30) -> g_X (fused) ===========
__global__ __launch_bounds__(256)
void k2_ln1(const float* __restrict__ node, const float* __restrict__ W3,
            const float* __restrict__ b3, const float* __restrict__ g1,
            const float* __restrict__ be1) {
    extern __shared__ float sm[];
    float* sS = sm;            // 32*128
    float* sW = sm + 4096;     // 128*128  sW[c][d] = W3[d*128 + c]
    float* sRs = sm + 20480;   // 512
    float* sRq = sm + 20992;   // 512
    const int tid = threadIdx.x, tx = tid & 15, ty = tid >> 4;
    const int n0 = blockIdx.x * 32;

#pragma unroll
    for (int m = 0; m < 4; ++m) {
        int f4 = tid + 256 * m;
        int r = f4 >> 5, c4 = f4 & 31;
        *(float4*)(sS + r * 128 + c4 * 4) =
            *(const float4*)(g_S + (size_t)(n0 + r) * 128 + c4 * 4);
    }
#pragma unroll
    for (int m = 0; m < 16; ++m) {
        int idx = tid + 256 * m;
        int d = idx & 127, c4 = idx >> 7;
        float4 v = *(const float4*)(W3 + (size_t)d * 128 + c4 * 4);
        sW[(c4 * 4 + 0) * 128 + d] = v.x;
        sW[(c4 * 4 + 1) * 128 + d] = v.y;
        sW[(c4 * 4 + 2) * 128 + d] = v.z;
        sW[(c4 * 4 + 3) * 128 + d] = v.w;
    }
    __syncthreads();

    float acc[2][8] = {};
#pragma unroll
    for (int kk = 0; kk < 128; kk += 4) {
        float a[2][4];
#pragma unroll
        for (int i = 0; i < 2; ++i) {
            float4 t = *(float4*)(sS + (ty + 16 * i) * 128 + kk);
            a[i][0] = t.x; a[i][1] = t.y; a[i][2] = t.z; a[i][3] = t.w;
        }
#pragma unroll
        for (int q = 0; q < 4; ++q) {
            float4 b0 = *(float4*)(sW + (kk + q) * 128 + tx * 8);
            float4 b1v = *(float4*)(sW + (kk + q) * 128 + tx * 8 + 4);
            float bb[8] = {b0.x, b0.y, b0.z, b0.w, b1v.x, b1v.y, b1v.z, b1v.w};
#pragma unroll
            for (int i = 0; i < 2; ++i)
#pragma unroll
                for (int j = 0; j < 8; ++j) acc[i][j] += a[i][q] * bb[j];
        }
    }

    float xv[2][8];
    float4 b30 = *(const float4*)(b3 + tx * 8);
    float4 b31 = *(const float4*)(b3 + tx * 8 + 4);
    float b3v[8] = {b30.x, b30.y, b30.z, b30.w, b31.x, b31.y, b31.z, b31.w};
#pragma unroll
    for (int i = 0; i < 2; ++i) {
        int r = ty + 16 * i, n = n0 + r;
        float As = g_A[n];
        float4 nv0 = *(const float4*)(node + (size_t)n * 128 + tx * 8);
        float4 nv1 = *(const float4*)(node + (size_t)n * 128 + tx * 8 + 4);
        float nb[8] = {nv0.x, nv0.y, nv0.z, nv0.w, nv1.x, nv1.y, nv1.z, nv1.w};
        float s = 0.f, q = 0.f;
#pragma unroll
        for (int j = 0; j < 8; ++j) {
            float v = nb[j] + (acc[i][j] + As * b3v[j]) * (1.0f / 30.0f);
            xv[i][j] = v; s += v; q += v * v;
        }
        sRs[r * 16 + tx] = s;
        sRq[r * 16 + tx] = q;
    }
    __syncthreads();
    float4 ga = *(const float4*)(g1 + tx * 8);
    float4 gb = *(const float4*)(g1 + tx * 8 + 4);
    float4 ea = *(const float4*)(be1 + tx * 8);
    float4 ebv = *(const float4*)(be1 + tx * 8 + 4);
    float gv[8] = {ga.x, ga.y, ga.z, ga.w, gb.x, gb.y, gb.z, gb.w};
    float ev[8] = {ea.x, ea.y, ea.z, ea.w, ebv.x, ebv.y, ebv.z, ebv.w};
#pragma unroll
    for (int i = 0; i < 2; ++i) {
        int r = ty + 16 * i;
        float s = 0.f, q = 0.f;
#pragma unroll
        for (int t = 0; t < 16; ++t) { s += sRs[r * 16 + t]; q += sRq[r * 16 + t]; }
        float mu = s * (1.0f / 128.0f);
        float var = q * (1.0f / 128.0f) - mu * mu;
        float rs = rsqrtf(var + 1e-5f);
        float o[8];
#pragma unroll
        for (int j = 0; j < 8; ++j) o[j] = (xv[i][j] - mu) * rs * gv[j] + ev[j];
        *(float4*)(g_X + (size_t)(n0 + r) * 128 + tx * 8) = make_float4(o[0], o[1], o[2], o[3]);
        *(float4*)(g_X + (size_t)(n0 + r) * 128 + tx * 8 + 4) = make_float4(o[4], o[5], o[6], o[7]);
    }
}

// ================= K3: g_H = gelu(g_X @ Wd1^T + bd1)  (N=512) ===============
__global__ __launch_bounds__(256)
void k3_mlp1(const float* __restrict__ Wd1, const float* __restrict__ bd1) {
    extern __shared__ float sm[];
    float* sX = sm;          // 32*128
    float* sW = sm + 4096;   // 128*128 per n-tile: sW[k][h] = Wd1[(h0+h)*128 + k]
    const int tid = threadIdx.x, tx = tid & 15, ty = tid >> 4;
    const int n0 = blockIdx.x * 32;

#pragma unroll
    for (int m = 0; m < 4; ++m) {
        int f4 = tid + 256 * m;
        int r = f4 >> 5, c4 = f4 & 31;
        *(float4*)(sX + r * 128 + c4 * 4) =
            *(const float4*)(g_X + (size_t)(n0 + r) * 128 + c4 * 4);
    }

    for (int h0 = 0; h0 < 512; h0 += 128) {
        __syncthreads();
#pragma unroll
        for (int m = 0; m < 16; ++m) {
            int idx = tid + 256 * m;
            int h = idx & 127, k4 = idx >> 7;
            float4 v = *(const float4*)(Wd1 + (size_t)(h0 + h) * 128 + k4 * 4);
            sW[(k4 * 4 + 0) * 128 + h] = v.x;
            sW[(k4 * 4 + 1) * 128 + h] = v.y;
            sW[(k4 * 4 + 2) * 128 + h] = v.z;
            sW[(k4 * 4 + 3) * 128 + h] = v.w;
        }
        __syncthreads();
        float acc[2][8] = {};
#pragma unroll
        for (int kk = 0; kk < 128; kk += 4) {
            float a[2][4];
#pragma unroll
            for (int i = 0; i < 2; ++i) {
                float4 t = *(float4*)(sX + (ty + 16 * i) * 128 + kk);
                a[i][0] = t.x; a[i][1] = t.y; a[i][2] = t.z; a[i][3] = t.w;
            }
#pragma unroll
            for (int q = 0; q < 4; ++q) {
                float4 b0 = *(float4*)(sW + (kk + q) * 128 + tx * 8);
                float4 b1v = *(float4*)(sW + (kk + q) * 128 + tx * 8 + 4);
                float bb[8] = {b0.x, b0.y, b0.z, b0.w, b1v.x, b1v.y, b1v.z, b1v.w};
#pragma unroll
                for (int i = 0; i < 2; ++i)
#pragma unroll
                    for (int j = 0; j < 8; ++j) acc[i][j] += a[i][q] * bb[j];
            }
        }
#pragma unroll
        for (int i = 0; i < 2; ++i) {
            int r = n0 + ty + 16 * i;
#pragma unroll
            for (int j = 0; j < 8; ++j) {
                int h = h0 + tx * 8 + j;
                g_H[(size_t)r * 512 + h] = gelu_f(acc[i][j] + bd1[h]);
            }
        }
    }
}

// ===== K4: out = mask * LN2(g_X + g_H @ Wd2^T + bd2)  (K=512, N=128) ========
__global__ __launch_bounds__(256)
void k4_out(const float* __restrict__ Wd2, const float* __restrict__ bd2,
            const float* __restrict__ g2, const float* __restrict__ be2,
            const float* __restrict__ maskp, float* __restrict__ out) {
    extern __shared__ float sm[];
    float* sA = sm;            // 32*128 (k-tile of g_H)
    float* sW = sm + 4096;     // 128*128: sW[k][c] = Wd2[c*512 + k0 + k]
    float* sRs = sm + 20480;   // 512
    float* sRq = sm + 20992;   // 512
    const int tid = threadIdx.x, tx = tid & 15, ty = tid >> 4;
    const int n0 = blockIdx.x * 32;

    float acc[2][8] = {};
    for (int k0 = 0; k0 < 512; k0 += 128) {
        __syncthreads();
#pragma unroll
        for (int m = 0; m < 4; ++m) {
            int f4 = tid + 256 * m;
            int r = f4 >> 5, c4 = f4 & 31;
            *(float4*)(sA + r * 128 + c4 * 4) =
                *(const float4*)(g_H + (size_t)(n0 + r) * 512 + k0 + c4 * 4);
        }
#pragma unroll
        for (int m = 0; m < 16; ++m) {
            int idx = tid + 256 * m;
            int c = idx & 127, k4 = idx >> 7;
            float4 v = *(const float4*)(Wd2 + (size_t)c * 512 + k0 + k4 * 4);
            sW[(k4 * 4 + 0) * 128 + c] = v.x;
            sW[(k4 * 4 + 1) * 128 + c] = v.y;
            sW[(k4 * 4 + 2) * 128 + c] = v.z;
            sW[(k4 * 4 + 3) * 128 + c] = v.w;
        }
        __syncthreads();
#pragma unroll
        for (int kk = 0; kk < 128; kk += 4) {
            float a[2][4];
#pragma unroll
            for (int i = 0; i < 2; ++i) {
                float4 t = *(float4*)(sA + (ty + 16 * i) * 128 + kk);
                a[i][0] = t.x; a[i][1] = t.y; a[i][2] = t.z; a[i][3] = t.w;
            }
#pragma unroll
            for (int q = 0; q < 4; ++q) {
                float4 b0 = *(float4*)(sW + (kk + q) * 128 + tx * 8);
                float4 b1v = *(float4*)(sW + (kk + q) * 128 + tx * 8 + 4);
                float bb[8] = {b0.x, b0.y, b0.z, b0.w, b1v.x, b1v.y, b1v.z, b1v.w};
#pragma unroll
                for (int i = 0; i < 2; ++i)
#pragma unroll
                    for (int j = 0; j < 8; ++j) acc[i][j] += a[i][q] * bb[j];
            }
        }
    }

    float xv[2][8];
    float4 ba = *(const float4*)(bd2 + tx * 8);
    float4 bbv = *(const float4*)(bd2 + tx * 8 + 4);
    float bdv[8] = {ba.x, ba.y, ba.z, ba.w, bbv.x, bbv.y, bbv.z, bbv.w};
#pragma unroll
    for (int i = 0; i < 2; ++i) {
        int r = ty + 16 * i, n = n0 + r;
        float4 x0 = *(const float4*)(g_X + (size_t)n * 128 + tx * 8);
        float4 x1 = *(const float4*)(g_X + (size_t)n * 128 + tx * 8 + 4);
        float xb[8] = {x0.x, x0.y, x0.z, x0.w, x1.x, x1.y, x1.z, x1.w};
        float s = 0.f, q = 0.f;
#pragma unroll
        for (int j = 0; j < 8; ++j) {
            float v = xb[j] + acc[i][j] + bdv[j];
            xv[i][j] = v; s += v; q += v * v;
        }
        sRs[r * 16 + tx] = s;
        sRq[r * 16 + tx] = q;
    }
    __syncthreads();
    float4 ga = *(const float4*)(g2 + tx * 8);
    float4 gb = *(const float4*)(g2 + tx * 8 + 4);
    float4 ea = *(const float4*)(be2 + tx * 8);
    float4 ebv = *(const float4*)(be2 + tx * 8 + 4);
    float gv[8] = {ga.x, ga.y, ga.z, ga.w, gb.x, gb.y, gb.z, gb.w};
    float ev[8] = {ea.x, ea.y, ea.z, ea.w, ebv.x, ebv.y, ebv.z, ebv.w};
#pragma unroll
    for (int i = 0; i < 2; ++i) {
        int r = ty + 16 * i, n = n0 + r;
        float s = 0.f, q = 0.f;
#pragma unroll
        for (int t = 0; t < 16; ++t) { s += sRs[r * 16 + t]; q += sRq[r * 16 + t]; }
        float mu = s * (1.0f / 128.0f);
        float var = q * (1.0f / 128.0f) - mu * mu;
        float rs = rsqrtf(var + 1e-5f);
        float mk = maskp[n];
        float o[8];
#pragma unroll
        for (int j = 0; j < 8; ++j)
            o[j] = mk * ((xv[i][j] - mu) * rs * gv[j] + ev[j]);
        *(float4*)(out + (size_t)n * 128 + tx * 8) = make_float4(o[0], o[1], o[2], o[3]);
        *(float4*)(out + (size_t)n * 128 + tx * 8 + 4) = make_float4(o[4], o[5], o[6], o[7]);
    }
}

// ============================== launch =====================================
extern "C" void kernel_launch(void* const* d_in, const int* in_sizes, int n_in,
                              void* d_out, int out_size) {
    const float* node = (const float*)d_in[0];
    const float* edge = (const float*)d_in[1];
    const float* mask = (const float*)d_in[2];
    const float* attn = (const float*)d_in[3];
    const float* W1   = (const float*)d_in[4];
    const float* b1   = (const float*)d_in[5];
    const float* W2   = (const float*)d_in[6];
    const float* b2   = (const float*)d_in[7];
    const float* W3   = (const float*)d_in[8];
    const float* b3   = (const float*)d_in[9];
    const float* g1   = (const float*)d_in[10];
    const float* be1  = (const float*)d_in[11];
    const float* Wd1  = (const float*)d_in[12];
    const float* bd1  = (const float*)d_in[13];
    const float* Wd2  = (const float*)d_in[14];
    const float* bd2  = (const float*)d_in[15];
    const float* g2   = (const float*)d_in[16];
    const float* be2  = (const float*)d_in[17];
    float* out = (float*)d_out;

    const size_t s0 = (size_t)(4096 + 16384) * sizeof(float);
    const size_t s1 = (size_t)(16384 + 6144 + 128 + 64) * sizeof(float);
    const size_t s2 = (size_t)(4096 + 16384 + 512 + 512) * sizeof(float);
    const size_t s3 = (size_t)(4096 + 16384) * sizeof(float);
    const size_t s4 = (size_t)(4096 + 16384 + 512 + 512) * sizeof(float);

    cudaFuncSetAttribute(k0_node_pre, cudaFuncAttributeMaxDynamicSharedMemorySize, (int)s0);
    cudaFuncSetAttribute(k1_edges,    cudaFuncAttributeMaxDynamicSharedMemorySize, (int)s1);
    cudaFuncSetAttribute(k2_ln1,      cudaFuncAttributeMaxDynamicSharedMemorySize, (int)s2);
    cudaFuncSetAttribute(k3_mlp1,     cudaFuncAttributeMaxDynamicSharedMemorySize, (int)s3);
    cudaFuncSetAttribute(k4_out,      cudaFuncAttributeMaxDynamicSharedMemorySize, (int)s4);

    k0_node_pre<<<NN / 32, 256, s0>>>(node, W1, b1);
    k1_edges<<<NN, 256, s1>>>(edge, attn, W1, W2, b2);
    k2_ln1<<<NN / 32, 256, s2>>>(node, W3, b3, g1, be1);
    k3_mlp1<<<NN / 32, 256, s3>>>(Wd1, bd1);
    k4_out<<<NN / 32, 256, s4>>>(Wd2, bd2, g2, be2, mask, out);
}